// round 12
// baseline (speedup 1.0000x reference)
#include <cuda_runtime.h>
#include <cuda_bf16.h>

// AngularDescriptor via moment expansion (fused, one warp per atom).
// R12: occupancy push — __launch_bounds__(256, 8) (regs<=32) with reduced
// phase-1 live state (g stored to smem as computed). Otherwise identical to
// the R11 winner: posw float4 pack kernel + smem-staged padded c_table.
//   q[i,d,l] = 0.5 * ( sum_p a_{lp} T_p[d]  -  sum_j g_ij[d]^2 )
//   T_p[d]   = sum_{|alpha|=p} w_alpha (sum_j g_ij[d] u_j^alpha)^2

#define WPB 8
#define MAXN 10000

__device__ __align__(16) float4 g_posw[MAXN];

__constant__ float4 WSEL[20] = {
    {1.f,0.f,0.f,0.f},
    {0.f,1.f,0.f,0.f},{0.f,1.f,0.f,0.f},{0.f,1.f,0.f,0.f},
    {0.f,0.f,1.f,0.f},{0.f,0.f,1.f,0.f},{0.f,0.f,1.f,0.f},
    {0.f,0.f,2.f,0.f},{0.f,0.f,2.f,0.f},{0.f,0.f,2.f,0.f},
    {0.f,0.f,0.f,1.f},{0.f,0.f,0.f,1.f},{0.f,0.f,0.f,1.f},
    {0.f,0.f,0.f,3.f},{0.f,0.f,0.f,3.f},{0.f,0.f,0.f,3.f},
    {0.f,0.f,0.f,3.f},{0.f,0.f,0.f,3.f},{0.f,0.f,0.f,3.f},
    {0.f,0.f,0.f,6.f}
};
__constant__ float4 ACOEF[4] = {
    { 1.0f,  0.0f, 0.0f, 0.0f},
    { 0.0f,  1.0f, 0.0f, 0.0f},
    {-0.5f,  0.0f, 1.5f, 0.0f},
    { 0.0f, -1.5f, 0.0f, 2.5f}
};

__global__ __launch_bounds__(256) void pack_kernel(
    const int* __restrict__ types,
    const float* __restrict__ pos,
    int n)
{
    const int i = blockIdx.x * 256 + threadIdx.x;
    if (i < n) {
        g_posw[i] = make_float4(pos[i * 3 + 0], pos[i * 3 + 1], pos[i * 3 + 2],
                                __int_as_float(types[i]));
    }
}

__global__ __launch_bounds__(WPB * 32, 8) void ang_kernel(
    const int*   __restrict__ nbr,
    const float* __restrict__ ctab,
    float*       __restrict__ out,
    int natoms)
{
    // per-neighbor row, stride 28 floats:
    // [0:8) g[8] | [8+4*grp : 12+4*grp) grp monomial block | [24:28) 5th monomials
    __shared__ __align__(16) float sh[WPB][20 * 28];
    __shared__ __align__(16) float cs[16 * 68];   // c_table, padded rows
    const int warp = threadIdx.x >> 5;
    const int lane = threadIdx.x & 31;
    const int atom = blockIdx.x * WPB + warp;

    // stage c_table (1024 floats) into padded smem
    #pragma unroll
    for (int t = threadIdx.x; t < 1024; t += WPB * 32) {
        const int row = t >> 6, col = t & 63;
        cs[row * 68 + col] = ctab[t];
    }
    __syncthreads();

    if (atom >= natoms) return;
    float* S = sh[warp];

    // ---- Phase 1: per-neighbor g[8] + monomials (lanes 0..19) ----
    if (lane < 20) {
        const int n = nbr[atom * 20 + lane];
        const float4 pn = g_posw[n];
        const float4 pa = g_posw[atom];
        const int ti = __float_as_int(pa.w);
        const int tj = __float_as_int(pn.w);

        const float dx = pn.x - pa.x;
        const float dy = pn.y - pa.y;
        const float dz = pn.z - pa.z;

        const float r2 = dx * dx + dy * dy + dz * dz;
        const float rinv = rsqrtf(r2);
        const float r  = r2 * rinv;

        const float fc = (r < 5.0f) ? fmaf(0.5f, __cosf(r * 0.6283185307179586f), 0.5f)
                                    : 0.0f;
        const float xr = fmaf(r, 0.2f, -1.0f);
        const float xx = fmaf(2.0f * xr, xr, -1.0f);
        const float h  = 0.5f * fc;

        float f[8];
        {
            float tp = 1.0f, tc = xx;
            f[0] = (tp + 1.0f) * h;
            f[1] = (tc + 1.0f) * h;
            #pragma unroll
            for (int k = 2; k < 8; k++) {
                const float tn = fmaf(2.0f * xx, tc, -tp);
                f[k] = (tn + 1.0f) * h;
                tp = tc; tc = tn;
            }
        }

        const float4* c4 = reinterpret_cast<const float4*>(cs + (ti * 4 + tj) * 68);
        float4* R = reinterpret_cast<float4*>(S + lane * 28);

        // store each g quartet as soon as it's ready (keeps <= 4 g live)
        #pragma unroll
        for (int q = 0; q < 2; q++) {
            float gq[4];
            #pragma unroll
            for (int t = 0; t < 4; t++) {
                const int dd = q * 4 + t;
                const float4 a = c4[dd * 2 + 0];
                const float4 b = c4[dd * 2 + 1];
                gq[t] = a.x * f[0] + a.y * f[1] + a.z * f[2] + a.w * f[3]
                      + b.x * f[4] + b.y * f[5] + b.z * f[6] + b.w * f[7];
            }
            R[q] = make_float4(gq[0], gq[1], gq[2], gq[3]);
        }

        const float x = dx * rinv, y = dy * rinv, z = dz * rinv;
        const float x2 = x * x, y2 = y * y, z2 = z * z;
        const float xy = x * y, xz = x * z, yz = y * z;

        R[2] = make_float4(1.0f,     x,       y,       z);       // grp0 block
        R[3] = make_float4(y2,       z2,      xy,      xz);      // grp1 block
        R[4] = make_float4(x2 * x,   y2 * y,  z2 * z,  x2 * y);  // grp2 block
        R[5] = make_float4(y2 * x,   y2 * z,  z2 * x,  z2 * y);  // grp3 block
        R[6] = make_float4(x2,       yz,      x2 * z,  xy * z);  // 5th monomials
    }
    __syncwarp();

    // ---- Phase 2: moment accumulation (3 LDS + 6 FMA per neighbor) ----
    const int d   = lane >> 2;
    const int grp = lane & 3;
    const float* Rg  = S + d;
    const float* Rm4 = S + 8 + 4 * grp;
    const float* Rm5 = S + 24 + grp;

    float M0 = 0.f, M1 = 0.f, M2 = 0.f, M3 = 0.f, M4 = 0.f, D = 0.f;
    #pragma unroll
    for (int j = 0; j < 20; j++) {
        const float  g  = Rg[j * 28];
        const float4 m4 = *reinterpret_cast<const float4*>(Rm4 + j * 28);
        const float  m5 = Rm5[j * 28];
        D  = fmaf(g, g,    D);
        M0 = fmaf(g, m4.x, M0);
        M1 = fmaf(g, m4.y, M1);
        M2 = fmaf(g, m4.z, M2);
        M3 = fmaf(g, m4.w, M3);
        M4 = fmaf(g, m5,   M4);
    }

    // ---- Epilogue: weighted squares into T buckets ----
    float T0 = 0.f, T1 = 0.f, T2 = 0.f, T3 = 0.f;
    {
        const float4* W = WSEL + grp * 5;
        float s; float4 w;
        s = M0 * M0; w = W[0];
        T0 = fmaf(s, w.x, T0); T1 = fmaf(s, w.y, T1); T2 = fmaf(s, w.z, T2); T3 = fmaf(s, w.w, T3);
        s = M1 * M1; w = W[1];
        T0 = fmaf(s, w.x, T0); T1 = fmaf(s, w.y, T1); T2 = fmaf(s, w.z, T2); T3 = fmaf(s, w.w, T3);
        s = M2 * M2; w = W[2];
        T0 = fmaf(s, w.x, T0); T1 = fmaf(s, w.y, T1); T2 = fmaf(s, w.z, T2); T3 = fmaf(s, w.w, T3);
        s = M3 * M3; w = W[3];
        T0 = fmaf(s, w.x, T0); T1 = fmaf(s, w.y, T1); T2 = fmaf(s, w.z, T2); T3 = fmaf(s, w.w, T3);
        s = M4 * M4; w = W[4];
        T0 = fmaf(s, w.x, T0); T1 = fmaf(s, w.y, T1); T2 = fmaf(s, w.z, T2); T3 = fmaf(s, w.w, T3);
    }

    // butterfly over the 4-lane d-group
    T0 += __shfl_xor_sync(0xffffffffu, T0, 1);
    T0 += __shfl_xor_sync(0xffffffffu, T0, 2);
    T1 += __shfl_xor_sync(0xffffffffu, T1, 1);
    T1 += __shfl_xor_sync(0xffffffffu, T1, 2);
    T2 += __shfl_xor_sync(0xffffffffu, T2, 1);
    T2 += __shfl_xor_sync(0xffffffffu, T2, 2);
    T3 += __shfl_xor_sync(0xffffffffu, T3, 1);
    T3 += __shfl_xor_sync(0xffffffffu, T3, 2);

    const float4 a = ACOEF[grp];
    float q = a.x * T0;
    q = fmaf(a.y, T1, q);
    q = fmaf(a.z, T2, q);
    q = fmaf(a.w, T3, q);
    out[atom * 32 + lane] = 0.5f * (q - D);
}

extern "C" void kernel_launch(void* const* d_in, const int* in_sizes, int n_in,
                              void* d_out, int out_size) {
    const int*   types = (const int*)  d_in[0];
    const float* pos   = (const float*)d_in[1];
    const int*   nbrs  = (const int*)  d_in[2];
    const float* ctab  = (const float*)d_in[3];
    float*       out   = (float*)      d_out;

    int natoms = in_sizes[0];
    if (natoms > MAXN) natoms = MAXN;

    pack_kernel<<<(natoms + 255) / 256, 256>>>(types, pos, natoms);
    ang_kernel<<<(natoms + WPB - 1) / WPB, WPB * 32>>>(nbrs, ctab, out, natoms);
}

// round 13
// speedup vs baseline: 1.1379x; 1.1379x over previous
#include <cuda_runtime.h>
#include <cuda_bf16.h>

// AngularDescriptor via moment expansion (one warp per atom).
// R13: (a) PDL — pack_kernel overlapped with ang_kernel prologue via
//      programmatic stream serialization + cudaGridDependencySynchronize();
//      (b) transposed smem layout: phase-2 LDS per lane 60 -> 30, all
//      conflict-free (G stride 20, M4 stride 84, M5 stride 24; bank starts
//      disjoint for the 8/4-way broadcast patterns).
//   q[i,d,l] = 0.5 * ( sum_p a_{lp} T_p[d]  -  sum_j g_ij[d]^2 )
//   T_p[d]   = sum_{|alpha|=p} w_alpha (sum_j g_ij[d] u_j^alpha)^2

#define WPB 8
#define MAXN 10000

// per-warp buffer: G[8][20] | M4[4][84] (each grp holds 20 float4) | M5[4][24]
#define GOFF  0
#define M4OFF 160
#define M5OFF 496
#define WBUF  592   // floats (2368B, 16B multiple)

__device__ __align__(16) float4 g_posw[MAXN];

__constant__ float4 WSEL[20] = {
    {1.f,0.f,0.f,0.f},
    {0.f,1.f,0.f,0.f},{0.f,1.f,0.f,0.f},{0.f,1.f,0.f,0.f},
    {0.f,0.f,1.f,0.f},{0.f,0.f,1.f,0.f},{0.f,0.f,1.f,0.f},
    {0.f,0.f,2.f,0.f},{0.f,0.f,2.f,0.f},{0.f,0.f,2.f,0.f},
    {0.f,0.f,0.f,1.f},{0.f,0.f,0.f,1.f},{0.f,0.f,0.f,1.f},
    {0.f,0.f,0.f,3.f},{0.f,0.f,0.f,3.f},{0.f,0.f,0.f,3.f},
    {0.f,0.f,0.f,3.f},{0.f,0.f,0.f,3.f},{0.f,0.f,0.f,3.f},
    {0.f,0.f,0.f,6.f}
};
__constant__ float4 ACOEF[4] = {
    { 1.0f,  0.0f, 0.0f, 0.0f},
    { 0.0f,  1.0f, 0.0f, 0.0f},
    {-0.5f,  0.0f, 1.5f, 0.0f},
    { 0.0f, -1.5f, 0.0f, 2.5f}
};

__global__ __launch_bounds__(256) void pack_kernel(
    const int* __restrict__ types,
    const float* __restrict__ pos,
    int n)
{
    const int i = blockIdx.x * 256 + threadIdx.x;
    if (i < n) {
        g_posw[i] = make_float4(pos[i * 3 + 0], pos[i * 3 + 1], pos[i * 3 + 2],
                                __int_as_float(types[i]));
    }
#if __CUDA_ARCH__ >= 900
    cudaTriggerProgrammaticLaunchCompletion();
#endif
}

__global__ __launch_bounds__(WPB * 32, 6) void ang_kernel(
    const int*   __restrict__ nbr,
    const float* __restrict__ ctab,
    float*       __restrict__ out,
    int natoms)
{
    __shared__ __align__(16) float sh[WPB][WBUF];
    __shared__ __align__(16) float cs[16 * 68];   // c_table, padded rows
    const int warp = threadIdx.x >> 5;
    const int lane = threadIdx.x & 31;
    const int atom = blockIdx.x * WPB + warp;

    // stage c_table (independent of pack_kernel) while pack may still run
    #pragma unroll
    for (int t = threadIdx.x; t < 1024; t += WPB * 32) {
        const int row = t >> 6, col = t & 63;
        cs[row * 68 + col] = ctab[t];
    }

    // nbr load is also independent of pack_kernel
    int n = 0;
    const bool active = (atom < natoms) && (lane < 20);
    if (active) n = nbr[atom * 20 + lane];

#if __CUDA_ARCH__ >= 900
    cudaGridDependencySynchronize();   // wait for g_posw before consuming it
#endif
    __syncthreads();

    if (atom >= natoms) return;
    float* S = sh[warp];

    // ---- Phase 1: per-neighbor g[8] + monomials (lanes 0..19) ----
    if (active) {
        const float4 pn = g_posw[n];
        const float4 pa = g_posw[atom];
        const int ti = __float_as_int(pa.w);
        const int tj = __float_as_int(pn.w);

        const float dx = pn.x - pa.x;
        const float dy = pn.y - pa.y;
        const float dz = pn.z - pa.z;

        const float r2 = dx * dx + dy * dy + dz * dz;
        const float rinv = rsqrtf(r2);
        const float r  = r2 * rinv;

        const float fc = (r < 5.0f) ? fmaf(0.5f, __cosf(r * 0.6283185307179586f), 0.5f)
                                    : 0.0f;
        const float xr = fmaf(r, 0.2f, -1.0f);
        const float xx = fmaf(2.0f * xr, xr, -1.0f);
        const float h  = 0.5f * fc;

        float f[8];
        {
            float tp = 1.0f, tc = xx;
            f[0] = (tp + 1.0f) * h;
            f[1] = (tc + 1.0f) * h;
            #pragma unroll
            for (int k = 2; k < 8; k++) {
                const float tn = fmaf(2.0f * xx, tc, -tp);
                f[k] = (tn + 1.0f) * h;
                tp = tc; tc = tn;
            }
        }

        const float4* c4 = reinterpret_cast<const float4*>(cs + (ti * 4 + tj) * 68);
        // G transposed: G[d][j]
        #pragma unroll
        for (int dd = 0; dd < 8; dd++) {
            const float4 a = c4[dd * 2 + 0];
            const float4 b = c4[dd * 2 + 1];
            S[GOFF + dd * 20 + lane] =
                  a.x * f[0] + a.y * f[1] + a.z * f[2] + a.w * f[3]
                + b.x * f[4] + b.y * f[5] + b.z * f[6] + b.w * f[7];
        }

        const float x = dx * rinv, y = dy * rinv, z = dz * rinv;
        const float x2 = x * x, y2 = y * y, z2 = z * z;
        const float xy = x * y, xz = x * z, yz = y * z;

        // M4[grp][j] as float4 blocks (stride 84 floats per grp)
        *reinterpret_cast<float4*>(S + M4OFF + 0 * 84 + lane * 4) =
            make_float4(1.0f,   x,      y,      z);
        *reinterpret_cast<float4*>(S + M4OFF + 1 * 84 + lane * 4) =
            make_float4(y2,     z2,     xy,     xz);
        *reinterpret_cast<float4*>(S + M4OFF + 2 * 84 + lane * 4) =
            make_float4(x2 * x, y2 * y, z2 * z, x2 * y);
        *reinterpret_cast<float4*>(S + M4OFF + 3 * 84 + lane * 4) =
            make_float4(y2 * x, y2 * z, z2 * x, z2 * y);
        // M5[grp][j] scalars (stride 24)
        S[M5OFF + 0 * 24 + lane] = x2;
        S[M5OFF + 1 * 24 + lane] = yz;
        S[M5OFF + 2 * 24 + lane] = x2 * z;
        S[M5OFF + 3 * 24 + lane] = xy * z;
    }
    __syncwarp();

    // ---- Phase 2: moment accumulation, vectorized loads ----
    const int d   = lane >> 2;
    const int grp = lane & 3;
    const float* Gd  = S + GOFF + d * 20;
    const float* M4g = S + M4OFF + grp * 84;
    const float* M5g = S + M5OFF + grp * 24;

    float M0 = 0.f, M1 = 0.f, M2 = 0.f, M3 = 0.f, M4a = 0.f, D = 0.f;
    #pragma unroll
    for (int t = 0; t < 5; t++) {
        const float4 g4  = *reinterpret_cast<const float4*>(Gd  + 4 * t);
        const float4 m54 = *reinterpret_cast<const float4*>(M5g + 4 * t);
        const float gs[4]  = {g4.x,  g4.y,  g4.z,  g4.w};
        const float m5s[4] = {m54.x, m54.y, m54.z, m54.w};
        #pragma unroll
        for (int s = 0; s < 4; s++) {
            const float  g  = gs[s];
            const float4 m4 = *reinterpret_cast<const float4*>(M4g + 4 * (4 * t + s));
            D   = fmaf(g, g,      D);
            M0  = fmaf(g, m4.x,   M0);
            M1  = fmaf(g, m4.y,   M1);
            M2  = fmaf(g, m4.z,   M2);
            M3  = fmaf(g, m4.w,   M3);
            M4a = fmaf(g, m5s[s], M4a);
        }
    }

    // ---- Epilogue: weighted squares into T buckets ----
    float T0 = 0.f, T1 = 0.f, T2 = 0.f, T3 = 0.f;
    {
        const float4* W = WSEL + grp * 5;
        float s; float4 w;
        s = M0 * M0;   w = W[0];
        T0 = fmaf(s, w.x, T0); T1 = fmaf(s, w.y, T1); T2 = fmaf(s, w.z, T2); T3 = fmaf(s, w.w, T3);
        s = M1 * M1;   w = W[1];
        T0 = fmaf(s, w.x, T0); T1 = fmaf(s, w.y, T1); T2 = fmaf(s, w.z, T2); T3 = fmaf(s, w.w, T3);
        s = M2 * M2;   w = W[2];
        T0 = fmaf(s, w.x, T0); T1 = fmaf(s, w.y, T1); T2 = fmaf(s, w.z, T2); T3 = fmaf(s, w.w, T3);
        s = M3 * M3;   w = W[3];
        T0 = fmaf(s, w.x, T0); T1 = fmaf(s, w.y, T1); T2 = fmaf(s, w.z, T2); T3 = fmaf(s, w.w, T3);
        s = M4a * M4a; w = W[4];
        T0 = fmaf(s, w.x, T0); T1 = fmaf(s, w.y, T1); T2 = fmaf(s, w.z, T2); T3 = fmaf(s, w.w, T3);
    }

    // butterfly over the 4-lane d-group
    T0 += __shfl_xor_sync(0xffffffffu, T0, 1);
    T0 += __shfl_xor_sync(0xffffffffu, T0, 2);
    T1 += __shfl_xor_sync(0xffffffffu, T1, 1);
    T1 += __shfl_xor_sync(0xffffffffu, T1, 2);
    T2 += __shfl_xor_sync(0xffffffffu, T2, 1);
    T2 += __shfl_xor_sync(0xffffffffu, T2, 2);
    T3 += __shfl_xor_sync(0xffffffffu, T3, 1);
    T3 += __shfl_xor_sync(0xffffffffu, T3, 2);

    const float4 a = ACOEF[grp];
    float q = a.x * T0;
    q = fmaf(a.y, T1, q);
    q = fmaf(a.z, T2, q);
    q = fmaf(a.w, T3, q);
    out[atom * 32 + lane] = 0.5f * (q - D);
}

extern "C" void kernel_launch(void* const* d_in, const int* in_sizes, int n_in,
                              void* d_out, int out_size) {
    const int*   types = (const int*)  d_in[0];
    const float* pos   = (const float*)d_in[1];
    const int*   nbrs  = (const int*)  d_in[2];
    const float* ctab  = (const float*)d_in[3];
    float*       out   = (float*)      d_out;

    int natoms = in_sizes[0];
    if (natoms > MAXN) natoms = MAXN;

    pack_kernel<<<(natoms + 255) / 256, 256>>>(types, pos, natoms);

    // ang launched with PDL: may start while pack is still running; the
    // device-side cudaGridDependencySynchronize() orders the posw reads.
    cudaLaunchConfig_t cfg = {};
    cfg.gridDim  = dim3((natoms + WPB - 1) / WPB, 1, 1);
    cfg.blockDim = dim3(WPB * 32, 1, 1);
    cudaLaunchAttribute attr[1];
    attr[0].id = cudaLaunchAttributeProgrammaticStreamSerialization;
    attr[0].val.programmaticStreamSerializationAllowed = 1;
    cfg.attrs = attr;
    cfg.numAttrs = 1;
    cudaLaunchKernelEx(&cfg, ang_kernel, nbrs, ctab, out, natoms);
}

// round 16
// speedup vs baseline: 1.1404x; 1.0022x over previous
#include <cuda_runtime.h>
#include <cuda_bf16.h>

// AngularDescriptor via moment expansion (warp per atom, edge-packed phase 1).
// R16 = R15 resubmitted verbatim (R15 hit "device busy" before any kernel ran
// — infra flake, not kernel). R15 = R14 + the missing __syncthreads() between
// c_table smem staging and phase 1 (R14's 4.5e-2 rel_err was a cs[] race).
//   - phase 1 processes the block's 160 edges on threads 0..159 (5 full warps
//     instead of 8 warps at 20/32 lanes) -> 37.5% fewer phase-1 instructions.
//   - per-neighbor smem rows (stride 28 floats), phase 2: 3 LDS + 6 FMA / nbr.
//   - pack_kernel (posw float4) overlapped via PDL.
//   q[i,d,l] = 0.5 * ( sum_p a_{lp} T_p[d]  -  sum_j g_ij[d]^2 )
//   T_p[d]   = sum_{|alpha|=p} w_alpha (sum_j g_ij[d] u_j^alpha)^2

#define WPB 8
#define MAXN 10000

__device__ __align__(16) float4 g_posw[MAXN];

__constant__ float4 WSEL[20] = {
    {1.f,0.f,0.f,0.f},
    {0.f,1.f,0.f,0.f},{0.f,1.f,0.f,0.f},{0.f,1.f,0.f,0.f},
    {0.f,0.f,1.f,0.f},{0.f,0.f,1.f,0.f},{0.f,0.f,1.f,0.f},
    {0.f,0.f,2.f,0.f},{0.f,0.f,2.f,0.f},{0.f,0.f,2.f,0.f},
    {0.f,0.f,0.f,1.f},{0.f,0.f,0.f,1.f},{0.f,0.f,0.f,1.f},
    {0.f,0.f,0.f,3.f},{0.f,0.f,0.f,3.f},{0.f,0.f,0.f,3.f},
    {0.f,0.f,0.f,3.f},{0.f,0.f,0.f,3.f},{0.f,0.f,0.f,3.f},
    {0.f,0.f,0.f,6.f}
};
__constant__ float4 ACOEF[4] = {
    { 1.0f,  0.0f, 0.0f, 0.0f},
    { 0.0f,  1.0f, 0.0f, 0.0f},
    {-0.5f,  0.0f, 1.5f, 0.0f},
    { 0.0f, -1.5f, 0.0f, 2.5f}
};

__global__ __launch_bounds__(256) void pack_kernel(
    const int* __restrict__ types,
    const float* __restrict__ pos,
    int n)
{
    const int i = blockIdx.x * 256 + threadIdx.x;
    if (i < n) {
        g_posw[i] = make_float4(pos[i * 3 + 0], pos[i * 3 + 1], pos[i * 3 + 2],
                                __int_as_float(types[i]));
    }
#if __CUDA_ARCH__ >= 900
    cudaTriggerProgrammaticLaunchCompletion();
#endif
}

__global__ __launch_bounds__(WPB * 32, 6) void ang_kernel(
    const int*   __restrict__ nbr,
    const float* __restrict__ ctab,
    float*       __restrict__ out,
    int natoms)
{
    // per-neighbor row, stride 28 floats:
    // [0:8) g[8] | [8+4*grp : 12+4*grp) grp monomial block | [24:28) 5th monomials
    __shared__ __align__(16) float sh[WPB][20 * 28];
    __shared__ __align__(16) float cs[16 * 68];   // c_table, padded rows
    const int tid  = threadIdx.x;
    const int warp = tid >> 5;
    const int lane = tid & 31;

    // stage c_table (independent of pack_kernel)
    #pragma unroll
    for (int t = tid; t < 1024; t += WPB * 32) {
        const int row = t >> 6, col = t & 63;
        cs[row * 68 + col] = ctab[t];
    }

    // edge assignment: threads 0..159 handle the block's 160 edges
    const int aw = tid / 20;          // atom within block (valid when tid<160)
    const int j  = tid - aw * 20;     // neighbor slot
    const int eatom = blockIdx.x * WPB + aw;
    const bool eactive = (tid < 160) && (eatom < natoms);

    int n = 0;
    if (eactive) n = nbr[eatom * 20 + j];   // independent of pack_kernel

#if __CUDA_ARCH__ >= 900
    cudaGridDependencySynchronize();   // g_posw ready beyond this point
#endif
    __syncthreads();                   // cs[] staging complete for ALL warps

    // ---- Phase 1: per-edge g[8] + monomials (threads 0..159) ----
    if (eactive) {
        const float4 pn = g_posw[n];
        const float4 pa = g_posw[eatom];
        const int ti = __float_as_int(pa.w);
        const int tj = __float_as_int(pn.w);

        const float dx = pn.x - pa.x;
        const float dy = pn.y - pa.y;
        const float dz = pn.z - pa.z;

        const float r2 = dx * dx + dy * dy + dz * dz;
        const float rinv = rsqrtf(r2);
        const float r  = r2 * rinv;

        const float fc = (r < 5.0f) ? fmaf(0.5f, __cosf(r * 0.6283185307179586f), 0.5f)
                                    : 0.0f;
        const float xr = fmaf(r, 0.2f, -1.0f);
        const float xx = fmaf(2.0f * xr, xr, -1.0f);
        const float h  = 0.5f * fc;

        float f[8];
        {
            float tp = 1.0f, tc = xx;
            f[0] = (tp + 1.0f) * h;
            f[1] = (tc + 1.0f) * h;
            #pragma unroll
            for (int k = 2; k < 8; k++) {
                const float tn = fmaf(2.0f * xx, tc, -tp);
                f[k] = (tn + 1.0f) * h;
                tp = tc; tc = tn;
            }
        }

        const float4* c4 = reinterpret_cast<const float4*>(cs + (ti * 4 + tj) * 68);
        float4* R = reinterpret_cast<float4*>(sh[aw] + j * 28);

        #pragma unroll
        for (int q = 0; q < 2; q++) {
            float gq[4];
            #pragma unroll
            for (int t = 0; t < 4; t++) {
                const int dd = q * 4 + t;
                const float4 a = c4[dd * 2 + 0];
                const float4 b = c4[dd * 2 + 1];
                gq[t] = a.x * f[0] + a.y * f[1] + a.z * f[2] + a.w * f[3]
                      + b.x * f[4] + b.y * f[5] + b.z * f[6] + b.w * f[7];
            }
            R[q] = make_float4(gq[0], gq[1], gq[2], gq[3]);
        }

        const float x = dx * rinv, y = dy * rinv, z = dz * rinv;
        const float x2 = x * x, y2 = y * y, z2 = z * z;
        const float xy = x * y, xz = x * z, yz = y * z;

        R[2] = make_float4(1.0f,     x,       y,       z);       // grp0 block
        R[3] = make_float4(y2,       z2,      xy,      xz);      // grp1 block
        R[4] = make_float4(x2 * x,   y2 * y,  z2 * z,  x2 * y);  // grp2 block
        R[5] = make_float4(y2 * x,   y2 * z,  z2 * x,  z2 * y);  // grp3 block
        R[6] = make_float4(x2,       yz,      x2 * z,  xy * z);  // 5th monomials
    }
    __syncthreads();

    const int atom = blockIdx.x * WPB + warp;
    if (atom >= natoms) return;
    float* S = sh[warp];

    // ---- Phase 2: moment accumulation (3 LDS + 6 FMA per neighbor) ----
    const int d   = lane >> 2;
    const int grp = lane & 3;
    const float* Rg  = S + d;
    const float* Rm4 = S + 8 + 4 * grp;
    const float* Rm5 = S + 24 + grp;

    float M0 = 0.f, M1 = 0.f, M2 = 0.f, M3 = 0.f, M4 = 0.f, D = 0.f;
    #pragma unroll
    for (int jj = 0; jj < 20; jj++) {
        const float  g  = Rg[jj * 28];
        const float4 m4 = *reinterpret_cast<const float4*>(Rm4 + jj * 28);
        const float  m5 = Rm5[jj * 28];
        D  = fmaf(g, g,    D);
        M0 = fmaf(g, m4.x, M0);
        M1 = fmaf(g, m4.y, M1);
        M2 = fmaf(g, m4.z, M2);
        M3 = fmaf(g, m4.w, M3);
        M4 = fmaf(g, m5,   M4);
    }

    // ---- Epilogue: weighted squares into T buckets ----
    float T0 = 0.f, T1 = 0.f, T2 = 0.f, T3 = 0.f;
    {
        const float4* W = WSEL + grp * 5;
        float s; float4 w;
        s = M0 * M0; w = W[0];
        T0 = fmaf(s, w.x, T0); T1 = fmaf(s, w.y, T1); T2 = fmaf(s, w.z, T2); T3 = fmaf(s, w.w, T3);
        s = M1 * M1; w = W[1];
        T0 = fmaf(s, w.x, T0); T1 = fmaf(s, w.y, T1); T2 = fmaf(s, w.z, T2); T3 = fmaf(s, w.w, T3);
        s = M2 * M2; w = W[2];
        T0 = fmaf(s, w.x, T0); T1 = fmaf(s, w.y, T1); T2 = fmaf(s, w.z, T2); T3 = fmaf(s, w.w, T3);
        s = M3 * M3; w = W[3];
        T0 = fmaf(s, w.x, T0); T1 = fmaf(s, w.y, T1); T2 = fmaf(s, w.z, T2); T3 = fmaf(s, w.w, T3);
        s = M4 * M4; w = W[4];
        T0 = fmaf(s, w.x, T0); T1 = fmaf(s, w.y, T1); T2 = fmaf(s, w.z, T2); T3 = fmaf(s, w.w, T3);
    }

    // butterfly over the 4-lane d-group
    T0 += __shfl_xor_sync(0xffffffffu, T0, 1);
    T0 += __shfl_xor_sync(0xffffffffu, T0, 2);
    T1 += __shfl_xor_sync(0xffffffffu, T1, 1);
    T1 += __shfl_xor_sync(0xffffffffu, T1, 2);
    T2 += __shfl_xor_sync(0xffffffffu, T2, 1);
    T2 += __shfl_xor_sync(0xffffffffu, T2, 2);
    T3 += __shfl_xor_sync(0xffffffffu, T3, 1);
    T3 += __shfl_xor_sync(0xffffffffu, T3, 2);

    const float4 a = ACOEF[grp];
    float q = a.x * T0;
    q = fmaf(a.y, T1, q);
    q = fmaf(a.z, T2, q);
    q = fmaf(a.w, T3, q);
    out[atom * 32 + lane] = 0.5f * (q - D);
}

extern "C" void kernel_launch(void* const* d_in, const int* in_sizes, int n_in,
                              void* d_out, int out_size) {
    const int*   types = (const int*)  d_in[0];
    const float* pos   = (const float*)d_in[1];
    const int*   nbrs  = (const int*)  d_in[2];
    const float* ctab  = (const float*)d_in[3];
    float*       out   = (float*)      d_out;

    int natoms = in_sizes[0];
    if (natoms > MAXN) natoms = MAXN;

    pack_kernel<<<(natoms + 255) / 256, 256>>>(types, pos, natoms);

    cudaLaunchConfig_t cfg = {};
    cfg.gridDim  = dim3((natoms + WPB - 1) / WPB, 1, 1);
    cfg.blockDim = dim3(WPB * 32, 1, 1);
    cudaLaunchAttribute attr[1];
    attr[0].id = cudaLaunchAttributeProgrammaticStreamSerialization;
    attr[0].val.programmaticStreamSerializationAllowed = 1;
    cfg.attrs = attr;
    cfg.numAttrs = 1;
    cudaLaunchKernelEx(&cfg, ang_kernel, nbrs, ctab, out, natoms);
}